// round 10
// baseline (speedup 1.0000x reference)
#include <cuda_runtime.h>
#include <cuda_bf16.h>
#include <math.h>

#define B_    128
#define Q_    16
#define D_    1024
#define E_    300
#define K_    11
#define CTAS_PER_B 8
#define DOCS_PER_CTA (D_/CTAS_PER_B)   // 128
#define THREADS1 128
#define NPAIR 64                       // thread pairs (t, t+64)
#define E4    (E_/4)                   // 75 f4
#define H0N   38                       // half0: f4 [0,38)
#define H1N   37                       // half1: f4 [38,75)
#define QSTRIDE 304                    // floats (76 f4)
#define Q4S   (QSTRIDE/4)
#define SSTRIDE 136                    // mod 32 == 8 -> conflict-free RBF access

// partials: [1024 CTAs][16 q][13]
__device__ float g_part[B_*CTAS_PER_B*Q_*13];
__device__ int   g_count[B_];

__global__ __launch_bounds__(THREADS1, 7)
void knrm_part_kernel(const int* __restrict__ doctoks,
                      const int* __restrict__ querytoks,
                      const float* __restrict__ emb,
                      const float* __restrict__ mus,
                      const float* __restrict__ sigmas,
                      const float* __restrict__ fc_w,
                      const float* __restrict__ fc_b,
                      float* __restrict__ out)
{
    __shared__ float qn[Q_*QSTRIDE];       // 16 x 304
    __shared__ float s_sh[Q_*SSTRIDE];     // 16 x 136
    __shared__ float ddtmp[DOCS_PER_CTA];  // half1 dd partials
    __shared__ float tmp16[16];
    __shared__ int last_flag;

    const int tid  = threadIdx.x;
    const int b    = blockIdx.x >> 3;
    const int cta  = blockIdx.x & 7;
    const int pr   = tid & (NPAIR-1);      // pair id 0..63
    const int half = tid >> 6;             // warps 0-1: half0, warps 2-3: half1

    // ---- load + normalize query embeddings into shared ----
    for (int i = tid; i < Q_*E_; i += THREADS1) {
        int q = i / E_, e = i - q*E_;
        int t = querytoks[b*Q_ + q];
        qn[q*QSTRIDE + e] = emb[t*E_ + e];
    }
    __syncthreads();
    {
        int q = tid >> 3, l = tid & 7;     // 16 q-rows x 8 lanes
        float ss = 0.f;
        for (int e = l; e < E_; e += 8) { float v = qn[q*QSTRIDE + e]; ss += v*v; }
        #pragma unroll
        for (int o = 4; o > 0; o >>= 1) ss += __shfl_down_sync(0xffffffffu, ss, o, 8);
        if (l == 0) tmp16[q] = 1.0f / (sqrtf(ss) + 1e-9f);
    }
    __syncthreads();
    for (int i = tid; i < Q_*E_; i += THREADS1) {
        int q = i / E_, e = i - q*E_;
        qn[q*QSTRIDE + e] *= tmp16[q];
    }
    __syncthreads();

    // ---- dot products: pair (t, t+64) shares docs (pr, pr+64);
    //      half0 covers f4 [0,38), half1 covers [38,75) ----
    const int t0 = doctoks[b*D_ + cta*DOCS_PER_CTA + pr];
    const int t1 = doctoks[b*D_ + cta*DOCS_PER_CTA + pr + 64];
    const float4* p0 = reinterpret_cast<const float4*>(emb) + (long)t0 * E4;
    const float4* p1 = reinterpret_cast<const float4*>(emb) + (long)t1 * E4;
    const float4* qn4 = reinterpret_cast<const float4*>(qn);

    float acc0[Q_], acc1[Q_];
    #pragma unroll
    for (int q = 0; q < Q_; q++) { acc0[q] = 0.f; acc1[q] = 0.f; }
    float dd0 = 0.f, dd1 = 0.f;

    auto fmastep = [&](const float4 a, const float4 c, int idx) {
        dd0 = fmaf(a.x,a.x, fmaf(a.y,a.y, fmaf(a.z,a.z, fmaf(a.w,a.w, dd0))));
        dd1 = fmaf(c.x,c.x, fmaf(c.y,c.y, fmaf(c.z,c.z, fmaf(c.w,c.w, dd1))));
        #pragma unroll
        for (int q = 0; q < Q_; q++) {
            float4 v = qn4[q*Q4S + idx];
            acc0[q] = fmaf(a.x,v.x, fmaf(a.y,v.y, fmaf(a.z,v.z, fmaf(a.w,v.w, acc0[q]))));
            acc1[q] = fmaf(c.x,v.x, fmaf(c.y,v.y, fmaf(c.z,v.z, fmaf(c.w,v.w, acc1[q]))));
        }
    };

    if (half == 0) {
        // f4 indices 0..37, depth-2 rolling prefetch, no predicates
        float4 a0 = p0[0], c0 = p1[0];
        float4 a1 = p0[1], c1 = p1[1];
        #pragma unroll 6
        for (int j = 0; j < H0N-2; j++) {          // j+2 <= 37, valid
            float4 an = p0[j+2];
            float4 cn = p1[j+2];
            fmastep(a0, c0, j);
            a0 = a1; c0 = c1; a1 = an; c1 = cn;
        }
        fmastep(a0, c0, H0N-2);
        fmastep(a1, c1, H0N-1);
    } else {
        // f4 indices 38..74
        float4 a0 = p0[38], c0 = p1[38];
        float4 a1 = p0[39], c1 = p1[39];
        #pragma unroll 5
        for (int j = 0; j < H1N-2; j++) {          // 38+j+2 <= 74, valid
            float4 an = p0[38 + j+2];
            float4 cn = p1[38 + j+2];
            fmastep(a0, c0, 38 + j);
            a0 = a1; c0 = c1; a1 = an; c1 = cn;
        }
        fmastep(a0, c0, 38 + H1N-2);
        fmastep(a1, c1, 38 + H1N-1);
    }

    // ---- combine halves via shared memory (once) ----
    if (half == 1) {
        #pragma unroll
        for (int q = 0; q < Q_; q++) {
            s_sh[q*SSTRIDE + pr]      = acc0[q];
            s_sh[q*SSTRIDE + pr + 64] = acc1[q];
        }
        ddtmp[pr]      = dd0;
        ddtmp[pr + 64] = dd1;
    }
    __syncthreads();
    if (half == 0) {
        const float inv0 = 1.0f / (sqrtf(dd0 + ddtmp[pr])      + 1e-9f);
        const float inv1 = 1.0f / (sqrtf(dd1 + ddtmp[pr + 64]) + 1e-9f);
        #pragma unroll
        for (int q = 0; q < Q_; q++) {
            s_sh[q*SSTRIDE + pr]      = (acc0[q] + s_sh[q*SSTRIDE + pr])      * inv0;
            s_sh[q*SSTRIDE + pr + 64] = (acc1[q] + s_sh[q*SSTRIDE + pr + 64]) * inv1;
        }
    }
    __syncthreads();

    // ---- RBF bank: 8 threads per q, each covers 16 docs ----
    const int myq = tid >> 3, myl = tid & 7;
    float mu_r[K_], w_r[K_];
    #pragma unroll
    for (int k = 0; k < K_; k++) {
        mu_r[k] = mus[k];
        float sg = sigmas[k];
        w_r[k] = -0.5f/(sg*sg);
    }
    float kacc[K_];
    #pragma unroll
    for (int k = 0; k < K_; k++) kacc[k] = 0.f;
    float simacc = 0.f;

    #pragma unroll 4
    for (int j = myl; j < DOCS_PER_CTA; j += 8) {
        float s = s_sh[myq*SSTRIDE + j];
        simacc += s;
        #pragma unroll
        for (int k = 0; k < K_; k++) {
            float dif = s - mu_r[k];
            kacc[k] += __expf(w_r[k]*dif*dif);
        }
    }

    #pragma unroll
    for (int k = 0; k < K_; k++) {
        float v = kacc[k];
        #pragma unroll
        for (int o = 4; o > 0; o >>= 1) v += __shfl_down_sync(0xffffffffu, v, o, 8);
        kacc[k] = v;
    }
    {
        float v = simacc;
        #pragma unroll
        for (int o = 4; o > 0; o >>= 1) v += __shfl_down_sync(0xffffffffu, v, o, 8);
        simacc = v;
    }
    if (myl == 0) {
        float* dst = &g_part[(blockIdx.x*Q_ + myq)*13];
        #pragma unroll
        for (int k = 0; k < K_; k++) dst[k] = kacc[k];
        dst[11] = simacc;
    }

    // ---- fused finalization: last CTA of this batch reduces + scores ----
    __syncthreads();
    if (tid == 0) {
        __threadfence();
        int old = atomicAdd(&g_count[b], 1);
        last_flag = (old == CTAS_PER_B - 1);
    }
    __syncthreads();
    if (!last_flag) return;

    if (tid < 32) {
        __threadfence();
        const int lane2 = tid;
        const int q = lane2 & 15;
        const bool active = (lane2 < 16);

        float kb[K_];
        #pragma unroll
        for (int k = 0; k < K_; k++) kb[k] = 0.f;
        float sim = 0.f;
        #pragma unroll
        for (int cc = 0; cc < CTAS_PER_B; cc++) {
            const float* src = &g_part[((b*CTAS_PER_B + cc)*Q_ + q)*13];
            #pragma unroll
            for (int k = 0; k < K_; k++) kb[k] += src[k];
            sim += src[11];
        }
        const bool m = (sim != 0.0f) && active;
        float score = fc_b[0];
        #pragma unroll
        for (int k = 0; k < K_; k++) {
            float v = m ? logf(kb[k] + 1e-6f) : 0.0f;
            #pragma unroll
            for (int o = 8; o > 0; o >>= 1) v += __shfl_down_sync(0xffffffffu, v, o, 16);
            score = fmaf(v, fc_w[k], score);
        }
        if (lane2 == 0) {
            out[b] = score;
            g_count[b] = 0;
        }
    }
}

extern "C" void kernel_launch(void* const* d_in, const int* in_sizes, int n_in,
                              void* d_out, int out_size)
{
    const int*   doctoks   = (const int*)  d_in[0];
    const int*   querytoks = (const int*)  d_in[1];
    // d_in[2] = query_idf (unused)
    const float* emb       = (const float*)d_in[3];
    const float* mus       = (const float*)d_in[4];
    const float* sigmas    = (const float*)d_in[5];
    const float* fc_w      = (const float*)d_in[6];
    const float* fc_b      = (const float*)d_in[7];
    float* out = (float*)d_out;

    knrm_part_kernel<<<B_*CTAS_PER_B, THREADS1>>>(
        doctoks, querytoks, emb, mus, sigmas, fc_w, fc_b, out);
}

// round 11
// speedup vs baseline: 1.8167x; 1.8167x over previous
#include <cuda_runtime.h>
#include <cuda_bf16.h>
#include <math.h>
#include <stdint.h>

#define B_    128
#define Q_    16
#define D_    1024
#define E_    300
#define K_    11
#define CTAS_PER_B 4
#define DOCS_PER_CTA (D_/CTAS_PER_B)   // 256
#define THREADS1 128
#define E4    (E_/4)                   // 75 float4
#define CH    5                        // f4 per chunk
#define NCHUNK (E4/CH)                 // 15
#define QSTRIDE 304                    // floats (76 f4)
#define Q4S   (QSTRIDE/4)
#define SSTRIDE 264                    // mod 32 == 8 -> conflict-free 8-lane groups

// dynamic smem layout (floats):
//   qn    : 16*304        = 4864   [0, 4864)
//   tmp16 : 16                     [4864, 4880)
//   stg   : 2*2*5*128 f4  = 10240  [4880, 15120)   (s_sh 16*264=4224 aliases stg)
#define SM_QN    0
#define SM_TMP   (Q_*QSTRIDE)
#define SM_STG   (SM_TMP + 16)
#define SM_FLOATS (SM_STG + 2*2*CH*THREADS1*4)

__device__ float g_part[B_*CTAS_PER_B*Q_*13];
__device__ int   g_count[B_];

__device__ __forceinline__ void cp16(uint32_t smem, const float4* g) {
    asm volatile("cp.async.cg.shared.global [%0], [%1], 16;\n" :: "r"(smem), "l"(g));
}

__global__ __launch_bounds__(THREADS1, 3)
void knrm_part_kernel(const int* __restrict__ doctoks,
                      const int* __restrict__ querytoks,
                      const float* __restrict__ emb,
                      const float* __restrict__ mus,
                      const float* __restrict__ sigmas,
                      const float* __restrict__ fc_w,
                      const float* __restrict__ fc_b,
                      float* __restrict__ out)
{
    extern __shared__ float sm[];
    __shared__ int last_flag;
    float* qn    = sm + SM_QN;
    float* tmp16 = sm + SM_TMP;
    float4* stg4 = reinterpret_cast<float4*>(sm + SM_STG);
    float* s_sh  = sm + SM_STG;            // aliases stg (used after pipeline drains)

    const int tid   = threadIdx.x;
    const int b     = blockIdx.x >> 2;
    const int cta   = blockIdx.x & 3;
    const int dbase = cta * DOCS_PER_CTA;

    // ---- load + normalize query embeddings into shared ----
    for (int i = tid; i < Q_*E_; i += THREADS1) {
        int q = i / E_, e = i - q*E_;
        int t = querytoks[b*Q_ + q];
        qn[q*QSTRIDE + e] = emb[t*E_ + e];
    }
    __syncthreads();
    {
        int q = tid >> 3, l = tid & 7;     // 16 q-rows x 8 lanes
        float ss = 0.f;
        for (int e = l; e < E_; e += 8) { float v = qn[q*QSTRIDE + e]; ss += v*v; }
        #pragma unroll
        for (int o = 4; o > 0; o >>= 1) ss += __shfl_down_sync(0xffffffffu, ss, o, 8);
        if (l == 0) tmp16[q] = 1.0f / (sqrtf(ss) + 1e-9f);
    }
    __syncthreads();
    for (int i = tid; i < Q_*E_; i += THREADS1) {
        int q = i / E_, e = i - q*E_;
        qn[q*QSTRIDE + e] *= tmp16[q];
    }
    __syncthreads();

    // ---- dot products: 2 docs/thread, cp.async double-buffered staging ----
    const int t0 = doctoks[b*D_ + dbase + tid];
    const int t1 = doctoks[b*D_ + dbase + tid + THREADS1];
    const float4* p0 = reinterpret_cast<const float4*>(emb) + (long)t0 * E4;
    const float4* p1 = reinterpret_cast<const float4*>(emb) + (long)t1 * E4;
    const float4* qn4 = reinterpret_cast<const float4*>(qn);

    uint32_t stg_base;
    {
        uint64_t tmpa;
        asm("cvta.to.shared.u64 %0, %1;" : "=l"(tmpa) : "l"(sm + SM_STG));
        stg_base = (uint32_t)tmpa;
    }
    // slot address: ((s*2+d)*CH + j)*THREADS1 + tid  (lane-major: conflict-free)
    auto slot = [&](int s, int d, int j) -> uint32_t {
        return stg_base + (uint32_t)((((s*2 + d)*CH + j)*THREADS1 + tid) * 16);
    };
    auto issue = [&](int k, int s) {
        #pragma unroll
        for (int j = 0; j < CH; j++) cp16(slot(s, 0, j), p0 + k*CH + j);
        #pragma unroll
        for (int j = 0; j < CH; j++) cp16(slot(s, 1, j), p1 + k*CH + j);
        asm volatile("cp.async.commit_group;");
    };

    float acc0[Q_], acc1[Q_];
    #pragma unroll
    for (int q = 0; q < Q_; q++) { acc0[q] = 0.f; acc1[q] = 0.f; }
    float dd0 = 0.f, dd1 = 0.f;

    auto fmastep = [&](const float4 a, const float4 c, int e4) {
        dd0 = fmaf(a.x,a.x, fmaf(a.y,a.y, fmaf(a.z,a.z, fmaf(a.w,a.w, dd0))));
        dd1 = fmaf(c.x,c.x, fmaf(c.y,c.y, fmaf(c.z,c.z, fmaf(c.w,c.w, dd1))));
        #pragma unroll
        for (int q = 0; q < Q_; q++) {
            float4 v = qn4[q*Q4S + e4];
            acc0[q] = fmaf(a.x,v.x, fmaf(a.y,v.y, fmaf(a.z,v.z, fmaf(a.w,v.w, acc0[q]))));
            acc1[q] = fmaf(c.x,v.x, fmaf(c.y,v.y, fmaf(c.z,v.z, fmaf(c.w,v.w, acc1[q]))));
        }
    };
    auto consume = [&](int c, int s) {
        #pragma unroll
        for (int j = 0; j < CH; j++) {
            float4 a = stg4[((s*2 + 0)*CH + j)*THREADS1 + tid];
            float4 cc = stg4[((s*2 + 1)*CH + j)*THREADS1 + tid];
            fmastep(a, cc, c*CH + j);
        }
    };

    issue(0, 0);
    issue(1, 1);
    for (int c = 0; c < NCHUNK-1; c++) {
        asm volatile("cp.async.wait_group 1;");   // chunk c complete
        int s = c & 1;
        consume(c, s);
        if (c + 2 < NCHUNK) issue(c + 2, s);
    }
    asm volatile("cp.async.wait_group 0;");       // last chunk complete, pipe drained
    consume(NCHUNK-1, (NCHUNK-1) & 1);

    const float inv0 = 1.0f / (sqrtf(dd0) + 1e-9f);
    const float inv1 = 1.0f / (sqrtf(dd1) + 1e-9f);

    // ---- transpose s into shared (aliases staging; all threads drained) ----
    __syncthreads();
    #pragma unroll
    for (int q = 0; q < Q_; q++) {
        s_sh[q*SSTRIDE + tid]            = acc0[q] * inv0;
        s_sh[q*SSTRIDE + tid + THREADS1] = acc1[q] * inv1;
    }
    __syncthreads();

    // ---- RBF bank: 8 threads per q, each covers 32 docs ----
    const int myq = tid >> 3, myl = tid & 7;
    float mu_r[K_], w_r[K_];
    #pragma unroll
    for (int k = 0; k < K_; k++) {
        mu_r[k] = mus[k];
        float sg = sigmas[k];
        w_r[k] = -0.5f/(sg*sg);
    }
    float kacc[K_];
    #pragma unroll
    for (int k = 0; k < K_; k++) kacc[k] = 0.f;
    float simacc = 0.f;

    #pragma unroll 4
    for (int j = myl; j < DOCS_PER_CTA; j += 8) {
        float s = s_sh[myq*SSTRIDE + j];
        simacc += s;
        #pragma unroll
        for (int k = 0; k < K_; k++) {
            float dif = s - mu_r[k];
            kacc[k] += __expf(w_r[k]*dif*dif);
        }
    }

    #pragma unroll
    for (int k = 0; k < K_; k++) {
        float v = kacc[k];
        #pragma unroll
        for (int o = 4; o > 0; o >>= 1) v += __shfl_down_sync(0xffffffffu, v, o, 8);
        kacc[k] = v;
    }
    {
        float v = simacc;
        #pragma unroll
        for (int o = 4; o > 0; o >>= 1) v += __shfl_down_sync(0xffffffffu, v, o, 8);
        simacc = v;
    }
    if (myl == 0) {
        float* dst = &g_part[(blockIdx.x*Q_ + myq)*13];
        #pragma unroll
        for (int k = 0; k < K_; k++) dst[k] = kacc[k];
        dst[11] = simacc;
    }

    // ---- fused finalization: last CTA of this batch reduces + scores ----
    __syncthreads();
    if (tid == 0) {
        __threadfence();
        int old = atomicAdd(&g_count[b], 1);
        last_flag = (old == CTAS_PER_B - 1);
    }
    __syncthreads();
    if (!last_flag) return;

    if (tid < 32) {
        __threadfence();
        const int lane = tid;
        const int q = lane & 15;
        const bool active = (lane < 16);

        float kb[K_];
        #pragma unroll
        for (int k = 0; k < K_; k++) kb[k] = 0.f;
        float sim = 0.f;
        #pragma unroll
        for (int cc = 0; cc < CTAS_PER_B; cc++) {
            const float* src = &g_part[((b*CTAS_PER_B + cc)*Q_ + q)*13];
            #pragma unroll
            for (int k = 0; k < K_; k++) kb[k] += src[k];
            sim += src[11];
        }
        const bool m = (sim != 0.0f) && active;
        float score = fc_b[0];
        #pragma unroll
        for (int k = 0; k < K_; k++) {
            float v = m ? logf(kb[k] + 1e-6f) : 0.0f;
            #pragma unroll
            for (int o = 8; o > 0; o >>= 1) v += __shfl_down_sync(0xffffffffu, v, o, 16);
            score = fmaf(v, fc_w[k], score);
        }
        if (lane == 0) {
            out[b] = score;
            g_count[b] = 0;
        }
    }
}

extern "C" void kernel_launch(void* const* d_in, const int* in_sizes, int n_in,
                              void* d_out, int out_size)
{
    const int*   doctoks   = (const int*)  d_in[0];
    const int*   querytoks = (const int*)  d_in[1];
    // d_in[2] = query_idf (unused)
    const float* emb       = (const float*)d_in[3];
    const float* mus       = (const float*)d_in[4];
    const float* sigmas    = (const float*)d_in[5];
    const float* fc_w      = (const float*)d_in[6];
    const float* fc_b      = (const float*)d_in[7];
    float* out = (float*)d_out;

    static bool attr_set = false;
    if (!attr_set) {
        cudaFuncSetAttribute(knrm_part_kernel,
                             cudaFuncAttributeMaxDynamicSharedMemorySize,
                             SM_FLOATS * (int)sizeof(float));
        attr_set = true;
    }
    knrm_part_kernel<<<B_*CTAS_PER_B, THREADS1, SM_FLOATS * (int)sizeof(float)>>>(
        doctoks, querytoks, emb, mus, sigmas, fc_w, fc_b, out);
}

// round 12
// speedup vs baseline: 2.3157x; 1.2747x over previous
#include <cuda_runtime.h>
#include <cuda_bf16.h>
#include <math.h>

#define B_    128
#define Q_    16
#define D_    1024
#define E_    300
#define K_    11
#define CTAS_PER_B 4
#define DOCS_PER_CTA (D_/CTAS_PER_B)   // 256
#define THREADS1 128
#define E4    (E_/4)                   // 75 float4
#define QSTRIDE 304                    // floats (76 f4)
#define Q4S   (QSTRIDE/4)
#define SSTRIDE 264                    // mod 32 == 8 -> conflict-free 8-lane groups

typedef unsigned long long u64;
union F4U { float4 f; u64 u[2]; };
union F2U { u64 u; float2 f; };

__device__ __forceinline__ void fma2(u64 &acc, u64 a, u64 b) {
    asm("fma.rn.f32x2 %0, %1, %2, %0;" : "+l"(acc) : "l"(a), "l"(b));
}

// partials: [512 CTAs][16 q][13] (11 kacc + 1 simacc + pad)
__device__ float g_part[B_*CTAS_PER_B*Q_*13];
__device__ int   g_count[B_];          // zero-init; reset by last CTA each run

__global__ __launch_bounds__(THREADS1, 3)
void knrm_part_kernel(const int* __restrict__ doctoks,
                      const int* __restrict__ querytoks,
                      const float* __restrict__ emb,
                      const float* __restrict__ mus,
                      const float* __restrict__ sigmas,
                      const float* __restrict__ fc_w,
                      const float* __restrict__ fc_b,
                      float* __restrict__ out)
{
    __shared__ float sm[Q_*QSTRIDE + 16];
    __shared__ int last_flag;
    float* qn    = sm;                // 16 x 304 ; later aliased as s_sh 16 x 264
    float* tmp16 = sm + Q_*QSTRIDE;

    const int tid   = threadIdx.x;
    const int b     = blockIdx.x >> 2;
    const int cta   = blockIdx.x & 3;
    const int dbase = cta * DOCS_PER_CTA;

    // ---- load + normalize query embeddings into shared ----
    for (int i = tid; i < Q_*E_; i += THREADS1) {
        int q = i / E_, e = i - q*E_;
        int t = querytoks[b*Q_ + q];
        qn[q*QSTRIDE + e] = emb[t*E_ + e];
    }
    __syncthreads();
    {
        int q = tid >> 3, l = tid & 7;     // 16 q-rows x 8 lanes
        float ss = 0.f;
        for (int e = l; e < E_; e += 8) { float v = qn[q*QSTRIDE + e]; ss += v*v; }
        #pragma unroll
        for (int o = 4; o > 0; o >>= 1) ss += __shfl_down_sync(0xffffffffu, ss, o, 8);
        if (l == 0) tmp16[q] = 1.0f / (sqrtf(ss) + 1e-9f);
    }
    __syncthreads();
    for (int i = tid; i < Q_*E_; i += THREADS1) {
        int q = i / E_, e = i - q*E_;
        qn[q*QSTRIDE + e] *= tmp16[q];
    }
    __syncthreads();

    // ---- dot products: 2 docs/thread, packed f32x2 FMA (FFMA2) ----
    const int t0 = doctoks[b*D_ + dbase + tid];
    const int t1 = doctoks[b*D_ + dbase + tid + THREADS1];
    const float4* p0 = reinterpret_cast<const float4*>(emb) + (long)t0 * E4;
    const float4* p1 = reinterpret_cast<const float4*>(emb) + (long)t1 * E4;
    const float4* qn4 = reinterpret_cast<const float4*>(qn);

    u64 acc0[Q_], acc1[Q_];
    #pragma unroll
    for (int q = 0; q < Q_; q++) { acc0[q] = 0ull; acc1[q] = 0ull; }
    u64 ddp0 = 0ull, ddp1 = 0ull;

    auto fmastep = [&](const F4U a, const F4U c, int e4) {
        fma2(ddp0, a.u[0], a.u[0]);
        fma2(ddp0, a.u[1], a.u[1]);
        fma2(ddp1, c.u[0], c.u[0]);
        fma2(ddp1, c.u[1], c.u[1]);
        #pragma unroll
        for (int q = 0; q < Q_; q++) {
            F4U v; v.f = qn4[q*Q4S + e4];
            fma2(acc0[q], a.u[0], v.u[0]);
            fma2(acc0[q], a.u[1], v.u[1]);
            fma2(acc1[q], c.u[0], v.u[0]);
            fma2(acc1[q], c.u[1], v.u[1]);
        }
    };

    // depth-2 rolling prefetch; main loop j<70 has j+2<=71 < 75 (no predicates)
    F4U a0, c0, a1, c1;
    a0.f = p0[0]; c0.f = p1[0];
    a1.f = p0[1]; c1.f = p1[1];
    #pragma unroll 5
    for (int j = 0; j < 70; j++) {
        F4U an, cn;
        an.f = p0[j+2];
        cn.f = p1[j+2];
        fmastep(a0, c0, j);
        a0 = a1; c0 = c1; a1 = an; c1 = cn;
    }
    #pragma unroll
    for (int j = 70; j < E4; j++) {
        F4U an, cn;
        if (j + 2 < E4) { an.f = p0[j+2]; cn.f = p1[j+2]; }
        else            { an.f = make_float4(0.f,0.f,0.f,0.f); cn = an; }
        fmastep(a0, c0, j);
        a0 = a1; c0 = c1; a1 = an; c1 = cn;
    }

    F2U dd0u, dd1u;
    dd0u.u = ddp0; dd1u.u = ddp1;
    const float dd0 = dd0u.f.x + dd0u.f.y;
    const float dd1 = dd1u.f.x + dd1u.f.y;
    const float inv0 = 1.0f / (sqrtf(dd0) + 1e-9f);
    const float inv1 = 1.0f / (sqrtf(dd1) + 1e-9f);

    // ---- transpose s into shared (aliases dead qn region) ----
    float* s_sh = sm;   // 16 x 264
    __syncthreads();    // all qn reads done
    #pragma unroll
    for (int q = 0; q < Q_; q++) {
        F2U u0, u1;
        u0.u = acc0[q]; u1.u = acc1[q];
        s_sh[q*SSTRIDE + tid]            = (u0.f.x + u0.f.y) * inv0;
        s_sh[q*SSTRIDE + tid + THREADS1] = (u1.f.x + u1.f.y) * inv1;
    }
    __syncthreads();

    // ---- RBF bank: 8 threads per q, each covers 32 docs ----
    const int myq = tid >> 3, myl = tid & 7;
    float mu_r[K_], w_r[K_];
    #pragma unroll
    for (int k = 0; k < K_; k++) {
        mu_r[k] = mus[k];
        float sg = sigmas[k];
        w_r[k] = -0.5f/(sg*sg);
    }
    float kacc[K_];
    #pragma unroll
    for (int k = 0; k < K_; k++) kacc[k] = 0.f;
    float simacc = 0.f;

    #pragma unroll 4
    for (int j = myl; j < DOCS_PER_CTA; j += 8) {
        float s = s_sh[myq*SSTRIDE + j];
        simacc += s;
        #pragma unroll
        for (int k = 0; k < K_; k++) {
            float dif = s - mu_r[k];
            kacc[k] += __expf(w_r[k]*dif*dif);
        }
    }

    // reduce over the 8 lanes of this q-group (contiguous lanes)
    #pragma unroll
    for (int k = 0; k < K_; k++) {
        float v = kacc[k];
        #pragma unroll
        for (int o = 4; o > 0; o >>= 1) v += __shfl_down_sync(0xffffffffu, v, o, 8);
        kacc[k] = v;
    }
    {
        float v = simacc;
        #pragma unroll
        for (int o = 4; o > 0; o >>= 1) v += __shfl_down_sync(0xffffffffu, v, o, 8);
        simacc = v;
    }
    if (myl == 0) {
        float* dst = &g_part[(blockIdx.x*Q_ + myq)*13];
        #pragma unroll
        for (int k = 0; k < K_; k++) dst[k] = kacc[k];
        dst[11] = simacc;
    }

    // ---- fused finalization: last CTA of this batch reduces + scores ----
    __syncthreads();
    if (tid == 0) {
        __threadfence();                       // release our partials
        int old = atomicAdd(&g_count[b], 1);
        last_flag = (old == CTAS_PER_B - 1);
    }
    __syncthreads();
    if (!last_flag) return;

    if (tid < 32) {
        __threadfence();                       // acquire other CTAs' partials
        const int lane = tid;
        const int q = lane & 15;               // lanes 16-31 duplicate; masked below
        const bool active = (lane < 16);

        float kb[K_];
        #pragma unroll
        for (int k = 0; k < K_; k++) kb[k] = 0.f;
        float sim = 0.f;
        #pragma unroll
        for (int cc = 0; cc < CTAS_PER_B; cc++) {
            const float* src = &g_part[((b*CTAS_PER_B + cc)*Q_ + q)*13];
            #pragma unroll
            for (int k = 0; k < K_; k++) kb[k] += src[k];
            sim += src[11];
        }
        const bool m = (sim != 0.0f) && active;
        float score = fc_b[0];
        #pragma unroll
        for (int k = 0; k < K_; k++) {
            float v = m ? logf(kb[k] + 1e-6f) : 0.0f;
            #pragma unroll
            for (int o = 8; o > 0; o >>= 1) v += __shfl_down_sync(0xffffffffu, v, o, 16);
            score = fmaf(v, fc_w[k], score);
        }
        if (lane == 0) {
            out[b] = score;
            g_count[b] = 0;                    // reset for next run / replay
        }
    }
}

extern "C" void kernel_launch(void* const* d_in, const int* in_sizes, int n_in,
                              void* d_out, int out_size)
{
    const int*   doctoks   = (const int*)  d_in[0];
    const int*   querytoks = (const int*)  d_in[1];
    // d_in[2] = query_idf (unused)
    const float* emb       = (const float*)d_in[3];
    const float* mus       = (const float*)d_in[4];
    const float* sigmas    = (const float*)d_in[5];
    const float* fc_w      = (const float*)d_in[6];
    const float* fc_b      = (const float*)d_in[7];
    float* out = (float*)d_out;

    knrm_part_kernel<<<B_*CTAS_PER_B, THREADS1>>>(
        doctoks, querytoks, emb, mus, sigmas, fc_w, fc_b, out);
}

// round 13
// speedup vs baseline: 2.4555x; 1.0604x over previous
#include <cuda_runtime.h>
#include <cuda_bf16.h>
#include <math.h>

#define B_    128
#define Q_    16
#define D_    1024
#define E_    300
#define K_    11
#define CTAS_PER_B 4
#define DOCS_PER_CTA (D_/CTAS_PER_B)   // 256
#define THREADS1 128
#define E4    (E_/4)                   // 75 float4
#define QSTRIDE 304                    // floats (76 f4)
#define SSTRIDE 264                    // mod 32 == 8 -> conflict-free 8-lane groups

// partials: [512 CTAs][16 q][13] (11 kacc + 1 simacc + pad)
__device__ float g_part[B_*CTAS_PER_B*Q_*13];
__device__ int   g_count[B_];          // zero-init; reset by last CTA each run

__global__ __launch_bounds__(THREADS1, 5)   // cap regs ~102 -> 5 CTAs/SM (20 warps)
void knrm_part_kernel(const int* __restrict__ doctoks,
                      const int* __restrict__ querytoks,
                      const float* __restrict__ emb,
                      const float* __restrict__ mus,
                      const float* __restrict__ sigmas,
                      const float* __restrict__ fc_w,
                      const float* __restrict__ fc_b,
                      float* __restrict__ out)
{
    __shared__ float sm[Q_*QSTRIDE + 16];
    __shared__ int last_flag;
    float* qn    = sm;                // 16 x 304 ; later aliased as s_sh 16 x 264
    float* tmp16 = sm + Q_*QSTRIDE;

    const int tid   = threadIdx.x;
    const int b     = blockIdx.x >> 2;
    const int cta   = blockIdx.x & 3;
    const int dbase = cta * DOCS_PER_CTA;

    // ---- load + normalize query embeddings into shared ----
    for (int i = tid; i < Q_*E_; i += THREADS1) {
        int q = i / E_, e = i - q*E_;
        int t = querytoks[b*Q_ + q];
        qn[q*QSTRIDE + e] = emb[t*E_ + e];
    }
    __syncthreads();
    {
        // 128 threads: 16 q-rows x 8 lanes each
        int q = tid >> 3, l = tid & 7;
        float ss = 0.f;
        for (int e = l; e < E_; e += 8) { float v = qn[q*QSTRIDE + e]; ss += v*v; }
        #pragma unroll
        for (int o = 4; o > 0; o >>= 1) ss += __shfl_down_sync(0xffffffffu, ss, o, 8);
        if (l == 0) tmp16[q] = 1.0f / (sqrtf(ss) + 1e-9f);
    }
    __syncthreads();
    for (int i = tid; i < Q_*E_; i += THREADS1) {
        int q = i / E_, e = i - q*E_;
        qn[q*QSTRIDE + e] *= tmp16[q];
    }
    __syncthreads();

    // ---- dot products: 2 docs/thread, rolling prefetch depth 2 ----
    const int t0 = doctoks[b*D_ + dbase + tid];
    const int t1 = doctoks[b*D_ + dbase + tid + THREADS1];
    const float4* p0 = reinterpret_cast<const float4*>(emb) + (long)t0 * E4;
    const float4* p1 = reinterpret_cast<const float4*>(emb) + (long)t1 * E4;
    const float4* qn4 = reinterpret_cast<const float4*>(qn);

    float acc0[Q_], acc1[Q_];
    #pragma unroll
    for (int q = 0; q < Q_; q++) { acc0[q] = 0.f; acc1[q] = 0.f; }
    float dd0 = 0.f, dd1 = 0.f;

    auto fmastep = [&](const float4 a, const float4 c, int e4) {
        dd0 = fmaf(a.x,a.x, fmaf(a.y,a.y, fmaf(a.z,a.z, fmaf(a.w,a.w, dd0))));
        dd1 = fmaf(c.x,c.x, fmaf(c.y,c.y, fmaf(c.z,c.z, fmaf(c.w,c.w, dd1))));
        #pragma unroll
        for (int q = 0; q < Q_; q++) {
            float4 v = qn4[q*(QSTRIDE/4) + e4];
            acc0[q] = fmaf(a.x,v.x, fmaf(a.y,v.y, fmaf(a.z,v.z, fmaf(a.w,v.w, acc0[q]))));
            acc1[q] = fmaf(c.x,v.x, fmaf(c.y,v.y, fmaf(c.z,v.z, fmaf(c.w,v.w, acc1[q]))));
        }
    };

    // depth-2 rolling prefetch; main loop j<70 has j+2<=71 < 75 (no predicates)
    float4 a0 = p0[0], c0 = p1[0];
    float4 a1 = p0[1], c1 = p1[1];
    #pragma unroll 5
    for (int j = 0; j < 70; j++) {
        float4 an = p0[j+2];
        float4 cn = p1[j+2];
        fmastep(a0, c0, j);
        a0 = a1; c0 = c1; a1 = an; c1 = cn;
    }
    #pragma unroll
    for (int j = 70; j < E4; j++) {
        float4 an, cn;
        if (j + 2 < E4) { an = p0[j+2]; cn = p1[j+2]; }
        else            { an = make_float4(0.f,0.f,0.f,0.f); cn = an; }
        fmastep(a0, c0, j);
        a0 = a1; c0 = c1; a1 = an; c1 = cn;
    }

    const float inv0 = 1.0f / (sqrtf(dd0) + 1e-9f);
    const float inv1 = 1.0f / (sqrtf(dd1) + 1e-9f);

    // ---- transpose s into shared (aliases dead qn region) ----
    float* s_sh = sm;   // 16 x 264
    __syncthreads();    // all qn reads done
    #pragma unroll
    for (int q = 0; q < Q_; q++) {
        s_sh[q*SSTRIDE + tid]            = acc0[q] * inv0;
        s_sh[q*SSTRIDE + tid + THREADS1] = acc1[q] * inv1;
    }
    __syncthreads();

    // ---- RBF bank: 8 threads per q, each covers 32 docs ----
    const int myq = tid >> 3, myl = tid & 7;
    float mu_r[K_], w_r[K_];
    #pragma unroll
    for (int k = 0; k < K_; k++) {
        mu_r[k] = mus[k];
        float sg = sigmas[k];
        w_r[k] = -0.5f/(sg*sg);
    }
    float kacc[K_];
    #pragma unroll
    for (int k = 0; k < K_; k++) kacc[k] = 0.f;
    float simacc = 0.f;

    #pragma unroll 4
    for (int j = myl; j < DOCS_PER_CTA; j += 8) {
        float s = s_sh[myq*SSTRIDE + j];
        simacc += s;
        #pragma unroll
        for (int k = 0; k < K_; k++) {
            float dif = s - mu_r[k];
            kacc[k] += __expf(w_r[k]*dif*dif);
        }
    }

    // reduce over the 8 lanes of this q-group (contiguous lanes)
    #pragma unroll
    for (int k = 0; k < K_; k++) {
        float v = kacc[k];
        #pragma unroll
        for (int o = 4; o > 0; o >>= 1) v += __shfl_down_sync(0xffffffffu, v, o, 8);
        kacc[k] = v;
    }
    {
        float v = simacc;
        #pragma unroll
        for (int o = 4; o > 0; o >>= 1) v += __shfl_down_sync(0xffffffffu, v, o, 8);
        simacc = v;
    }
    if (myl == 0) {
        float* dst = &g_part[(blockIdx.x*Q_ + myq)*13];
        #pragma unroll
        for (int k = 0; k < K_; k++) dst[k] = kacc[k];
        dst[11] = simacc;
    }

    // ---- fused finalization: last CTA of this batch reduces + scores ----
    __syncthreads();
    if (tid == 0) {
        __threadfence();                       // release our partials
        int old = atomicAdd(&g_count[b], 1);
        last_flag = (old == CTAS_PER_B - 1);
    }
    __syncthreads();
    if (!last_flag) return;

    if (tid < 32) {
        __threadfence();                       // acquire other CTAs' partials
        const int lane = tid;
        const int q = lane & 15;               // lanes 16-31 duplicate; masked below
        const bool active = (lane < 16);

        float kb[K_];
        #pragma unroll
        for (int k = 0; k < K_; k++) kb[k] = 0.f;
        float sim = 0.f;
        #pragma unroll
        for (int cc = 0; cc < CTAS_PER_B; cc++) {
            const float* src = &g_part[((b*CTAS_PER_B + cc)*Q_ + q)*13];
            #pragma unroll
            for (int k = 0; k < K_; k++) kb[k] += src[k];
            sim += src[11];
        }
        const bool m = (sim != 0.0f) && active;
        float score = fc_b[0];
        #pragma unroll
        for (int k = 0; k < K_; k++) {
            float v = m ? logf(kb[k] + 1e-6f) : 0.0f;
            #pragma unroll
            for (int o = 8; o > 0; o >>= 1) v += __shfl_down_sync(0xffffffffu, v, o, 16);
            score = fmaf(v, fc_w[k], score);
        }
        if (lane == 0) {
            out[b] = score;
            g_count[b] = 0;                    // reset for next run / replay
        }
    }
}

extern "C" void kernel_launch(void* const* d_in, const int* in_sizes, int n_in,
                              void* d_out, int out_size)
{
    const int*   doctoks   = (const int*)  d_in[0];
    const int*   querytoks = (const int*)  d_in[1];
    // d_in[2] = query_idf (unused)
    const float* emb       = (const float*)d_in[3];
    const float* mus       = (const float*)d_in[4];
    const float* sigmas    = (const float*)d_in[5];
    const float* fc_w      = (const float*)d_in[6];
    const float* fc_b      = (const float*)d_in[7];
    float* out = (float*)d_out;

    knrm_part_kernel<<<B_*CTAS_PER_B, THREADS1>>>(
        doctoks, querytoks, emb, mus, sigmas, fc_w, fc_b, out);
}